// round 13
// baseline (speedup 1.0000x reference)
#include <cuda_runtime.h>

#define B_ 8
#define C_ 64
#define H_ 256
#define W_ 256
#define E_ 256
#define NH_ 8
#define HD_ 32
#define NPIX (H_*W_)
#define PST 68

// smem floats: xs[16384] | la[3072] | w8[1024] | red[104] | srow[8] | sbv[8] | misc[8]
#define XS_F   (256*64)
#define LA_F   (256*12)
#define W8_F   (64*16)
#define RED_F  104
#define SMEM_FLOATS (XS_F + LA_F + W8_F + RED_F + 16 + 8)

__device__ float g_wa[B_*NH_*C_];
__device__ float g_wb[B_*NH_*C_];
__device__ float g_wc[B_*NH_*C_];
__device__ float g_s [B_*NH_*3];
__device__ float g_part[(size_t)B_*H_*NH_*PST];
__device__ int   g_flag[B_];     // zero-init; reset by combiner each run
__device__ int   g_cnt [B_];

#define FMA2(a, x, w) asm("fma.rn.f32x2 %0, %1, %2, %0;" : "+l"(a) : "l"(x), "l"(w))

__global__ void __launch_bounds__(128, 2) main_kernel(
    const float* __restrict__ x,  const float* __restrict__ z,
    const float* __restrict__ pos,
    const float* __restrict__ Wq, const float* __restrict__ bq,
    const float* __restrict__ Wk, const float* __restrict__ bk,
    const float* __restrict__ Wv, const float* __restrict__ bv,
    const float* __restrict__ Wp, const float* __restrict__ bp,
    float* __restrict__ out)
{
    extern __shared__ float sm[];
    float* xs   = sm;                      // [64 px-rows? swizzled 256x64]
    float* la   = sm + XS_F;               // [256][12]
    float* w8   = la + LA_F;               // [64][16]
    float* red  = w8 + W8_F;
    float* srow = red + RED_F;
    float* sbv  = srow + 8;
    int*   misc = (int*)(sbv + 8);
    float* red_m = red, *red_t = red + 32, *red_pj = red + 64, *mfin = red + 96;

    int row = blockIdx.x, b = blockIdx.y;
    int tid = threadIdx.x;
    int warp = tid >> 5, lane = tid & 31;
    const float sc = 0.1767766952966369f;  // 1/sqrt(32)

    // ================= producer prologue (row 0 blocks): prep for batch b ====
    if (row == 0) {
        float* tA = la;          // [256]
        float* tB = la + 256;
        float* tC = la + 512;
        float* zsh = la + 768;   // [64]
        if (tid < 16)
            reinterpret_cast<float4*>(zsh)[tid] =
                reinterpret_cast<const float4*>(z + b*C_)[tid];
        __syncthreads();
        #pragma unroll
        for (int halfE = 0; halfE < 2; halfE++) {
            int e = tid + halfE*128;
            int d = e & 31, h = e >> 5;
            const float4* wq = reinterpret_cast<const float4*>(Wq + e*C_);
            const float4* zv4 = reinterpret_cast<const float4*>(zsh);
            float acc = 0.f;
            #pragma unroll
            for (int k = 0; k < 16; k++) {
                float4 w = __ldg(wq + k);
                float4 zv = zv4[k];
                acc += w.x*zv.x + w.y*zv.y + w.z*zv.z + w.w*zv.w;
            }
            float qv = acc + bq[e];
            float wp0 = Wp[2*d], wp1 = Wp[2*d+1];
            float p0 = pos[(b*NH_+h)*2], p1 = pos[(b*NH_+h)*2+1];
            tA[e] = qv*wp0*sc;
            tB[e] = qv*wp1*sc;
            tC[e] = qv*(bp[d] - wp0*p0 - wp1*p1)*sc;
        }
        __syncthreads();
        // project through Wk: thread handles (c, 4 heads)
        {
            int c = tid & 63, hg = tid >> 6;
            #pragma unroll
            for (int j = 0; j < 4; j++) {
                int h = hg*4 + j;
                const float* wk = Wk + (h*HD_)*C_ + c;
                const float* ta = tA + h*HD_;
                const float* tb = tB + h*HD_;
                const float* tc = tC + h*HD_;
                float a = 0.f, bb2 = 0.f, cc = 0.f;
                #pragma unroll
                for (int d = 0; d < HD_; d++) {
                    float w = __ldg(wk + d*C_);
                    a += ta[d]*w; bb2 += tb[d]*w; cc += tc[d]*w;
                }
                int gi = (b*NH_+h)*C_ + c;
                g_wa[gi] = a; g_wb[gi] = bb2; g_wc[gi] = cc;
            }
        }
        if (tid < 24) {
            int h = tid / 3, i = tid % 3;
            const float* t = (i==0) ? (la + h*HD_) : ((i==1) ? (la+256+h*HD_) : (la+512+h*HD_));
            float sv = 0.f;
            #pragma unroll
            for (int d = 0; d < HD_; d++) sv += t[d]*bk[h*HD_ + d];
            g_s[(b*NH_+h)*3 + i] = sv;
        }
        __threadfence();
        __syncthreads();
        if (tid == 0) atomicExch(&g_flag[b], 1);
    }

    // ================= staging (r5): 2 batches of 16 LDG.128, swizzled STS ===
    {
        const float* xg = x + (size_t)b*C_*NPIX + (size_t)row*W_;
        #pragma unroll
        for (int half = 0; half < 2; half++) {
            float4 v[16];
            #pragma unroll
            for (int j = 0; j < 16; j++) {
                int idx = tid + (half*16 + j)*128;
                int c = idx >> 6, q = idx & 63;
                v[j] = __ldg(reinterpret_cast<const float4*>(xg + (size_t)c*NPIX) + q);
            }
            #pragma unroll
            for (int j = 0; j < 16; j++) {
                int idx = tid + (half*16 + j)*128;
                int c = idx >> 6, q = idx & 63;
                int base = q*4*64;
                xs[base       + ((c + q     ) & 63)] = v[j].x;
                xs[base + 64  + ((c + q +  8) & 63)] = v[j].y;
                xs[base + 128 + ((c + q + 16) & 63)] = v[j].z;
                xs[base + 192 + ((c + q + 24) & 63)] = v[j].w;
            }
        }
    }

    // wait for prep tables (consumers; producer's own flag already set)
    if (tid == 0) {
        while (atomicAdd(&g_flag[b], 0) == 0) __nanosleep(200);
    }
    __syncthreads();

    // per-row combined weights
    float rowf = (float)row;
    if (tid < 64) {
        int c = tid;
        #pragma unroll
        for (int h = 0; h < 8; h++) {
            int gi = (b*NH_+h)*C_ + c;
            w8[c*16 + 2*h]     = g_wc[gi] + rowf*g_wa[gi];
            w8[c*16 + 2*h + 1] = g_wb[gi];
        }
    } else if (tid < 72) {
        int h = tid - 64;
        srow[h] = g_s[(b*NH_+h)*3+2] + rowf*g_s[(b*NH_+h)*3+0];
        sbv[h]  = g_s[(b*NH_+h)*3+1];
    }
    __syncthreads();

    // ================= Phase A: logits, 2 px/thread (r5) =====================
    int p0 = tid, p1 = tid + 128;
    float l0[8], l1[8];
    {
        unsigned long long acc0[8], acc1[8];
        #pragma unroll
        for (int h = 0; h < 8; h++) { acc0[h] = 0ULL; acc1[h] = 0ULL; }
        const float* xr0 = xs + p0*64;
        const float* xr1 = xs + p1*64;
        int G0 = ((p0 & 3) << 3) + (p0 >> 2);
        int G1 = ((p1 & 3) << 3) + (p1 >> 2);
        #pragma unroll 4
        for (int c = 0; c < 64; c++) {
            float x0 = xr0[(c + G0) & 63];
            float x1 = xr1[(c + G1) & 63];
            unsigned long long xx0, xx1;
            asm("mov.b64 %0, {%1, %1};" : "=l"(xx0) : "f"(x0));
            asm("mov.b64 %0, {%1, %1};" : "=l"(xx1) : "f"(x1));
            const ulonglong2* wp = reinterpret_cast<const ulonglong2*>(w8 + c*16);
            ulonglong2 wA = wp[0], wB = wp[1];
            FMA2(acc0[0], xx0, wA.x);  FMA2(acc1[0], xx1, wA.x);
            FMA2(acc0[1], xx0, wA.y);  FMA2(acc1[1], xx1, wA.y);
            FMA2(acc0[2], xx0, wB.x);  FMA2(acc1[2], xx1, wB.x);
            FMA2(acc0[3], xx0, wB.y);  FMA2(acc1[3], xx1, wB.y);
            ulonglong2 wC = wp[2], wD = wp[3];
            FMA2(acc0[4], xx0, wC.x);  FMA2(acc1[4], xx1, wC.x);
            FMA2(acc0[5], xx0, wC.y);  FMA2(acc1[5], xx1, wC.y);
            FMA2(acc0[6], xx0, wD.x);  FMA2(acc1[6], xx1, wD.x);
            FMA2(acc0[7], xx0, wD.y);  FMA2(acc1[7], xx1, wD.y);
        }
        float c0f = (float)p0, c1f = (float)p1;
        #pragma unroll
        for (int h = 0; h < 8; h++) {
            float r, bb;
            asm("mov.b64 {%0, %1}, %2;" : "=f"(r), "=f"(bb) : "l"(acc0[h]));
            l0[h] = (r + srow[h]) + c0f*(bb + sbv[h]);
            asm("mov.b64 {%0, %1}, %2;" : "=f"(r), "=f"(bb) : "l"(acc1[h]));
            l1[h] = (r + srow[h]) + c1f*(bb + sbv[h]);
        }
    }

    // ================= softmax over the row (r5) =============================
    {
        float mh[8];
        #pragma unroll
        for (int h = 0; h < 8; h++) mh[h] = fmaxf(l0[h], l1[h]);
        #pragma unroll
        for (int o = 16; o; o >>= 1) {
            #pragma unroll
            for (int h = 0; h < 8; h++)
                mh[h] = fmaxf(mh[h], __shfl_xor_sync(0xffffffffu, mh[h], o));
        }
        if (lane == 0) {
            #pragma unroll
            for (int h = 0; h < 8; h++) red_m[warp*8 + h] = mh[h];
        }
        __syncthreads();
        if (tid < 8)
            mfin[tid] = fmaxf(fmaxf(red_m[tid], red_m[8+tid]),
                              fmaxf(red_m[16+tid], red_m[24+tid]));
        __syncthreads();

        float th[8], pjh[8], e0[8], e1[8];
        float c0f = (float)p0, c1f = (float)p1;
        #pragma unroll
        for (int h = 0; h < 8; h++) {
            float M = mfin[h];
            e0[h] = __expf(l0[h] - M);
            e1[h] = __expf(l1[h] - M);
            th[h]  = e0[h] + e1[h];
            pjh[h] = e0[h]*c0f + e1[h]*c1f;
        }
        *reinterpret_cast<float4*>(la + p0*12)     = make_float4(e0[0], e0[1], e0[2], e0[3]);
        *reinterpret_cast<float4*>(la + p0*12 + 4) = make_float4(e0[4], e0[5], e0[6], e0[7]);
        *reinterpret_cast<float4*>(la + p1*12)     = make_float4(e1[0], e1[1], e1[2], e1[3]);
        *reinterpret_cast<float4*>(la + p1*12 + 4) = make_float4(e1[4], e1[5], e1[6], e1[7]);

        #pragma unroll
        for (int o = 16; o; o >>= 1) {
            #pragma unroll
            for (int h = 0; h < 8; h++) {
                th[h]  += __shfl_xor_sync(0xffffffffu, th[h],  o);
                pjh[h] += __shfl_xor_sync(0xffffffffu, pjh[h], o);
            }
        }
        if (lane == 0) {
            #pragma unroll
            for (int h = 0; h < 8; h++) {
                red_t[warp*8 + h]  = th[h];
                red_pj[warp*8 + h] = pjh[h];
            }
        }
        __syncthreads();   // la + reductions ready
        if (tid < 8) {
            float T  = red_t[tid]  + red_t[8+tid]  + red_t[16+tid]  + red_t[24+tid];
            float PJ = red_pj[tid] + red_pj[8+tid] + red_pj[16+tid] + red_pj[24+tid];
            size_t pb = ((size_t)(b*H_ + row)*NH_ + tid)*PST;
            g_part[pb + 64] = mfin[tid];
            g_part[pb + 65] = T;
            g_part[pb + 66] = PJ;
        }
    }

    // ====== Phase B: thread = (c-pair, 64px quarter); la loads amortized =====
    {
        int c0 = tid & 31, c1 = c0 + 32, q4 = tid >> 5;
        unsigned long long a0[4], a1[4];
        #pragma unroll
        for (int j = 0; j < 4; j++) { a0[j] = 0ULL; a1[j] = 0ULL; }
        int pbase = q4*64;
        #pragma unroll 4
        for (int i = 0; i < 64; i++) {
            int p = pbase + i;
            int up = ((p & 3) << 3) + (p >> 2);
            float xv0 = xs[p*64 + ((c0 + up) & 63)];
            float xv1 = xs[p*64 + ((c1 + up) & 63)];
            unsigned long long xx0, xx1;
            asm("mov.b64 %0, {%1, %1};" : "=l"(xx0) : "f"(xv0));
            asm("mov.b64 %0, {%1, %1};" : "=l"(xx1) : "f"(xv1));
            ulonglong2 eA = *reinterpret_cast<const ulonglong2*>(la + p*12);
            ulonglong2 eB = *reinterpret_cast<const ulonglong2*>(la + p*12 + 4);
            FMA2(a0[0], xx0, eA.x);  FMA2(a1[0], xx1, eA.x);
            FMA2(a0[1], xx0, eA.y);  FMA2(a1[1], xx1, eA.y);
            FMA2(a0[2], xx0, eB.x);  FMA2(a1[2], xx1, eB.x);
            FMA2(a0[3], xx0, eB.y);  FMA2(a1[3], xx1, eB.y);
        }
        __syncthreads();            // all xs reads done; reuse xs for Sp[h][q][c]
        float* Sp = xs;             // [8][4][64]
        #pragma unroll
        for (int j = 0; j < 4; j++) {
            float f0, f1, f2, f3;
            asm("mov.b64 {%0, %1}, %2;" : "=f"(f0), "=f"(f1) : "l"(a0[j]));
            asm("mov.b64 {%0, %1}, %2;" : "=f"(f2), "=f"(f3) : "l"(a1[j]));
            Sp[(2*j  )*256 + q4*64 + c0] = f0;
            Sp[(2*j+1)*256 + q4*64 + c0] = f1;
            Sp[(2*j  )*256 + q4*64 + c1] = f2;
            Sp[(2*j+1)*256 + q4*64 + c1] = f3;
        }
        __syncthreads();
        if (tid < 64) {
            size_t gb = (size_t)(b*H_ + row)*NH_;
            #pragma unroll
            for (int h = 0; h < 8; h++) {
                const float* sp = Sp + h*256 + tid;
                g_part[(gb + h)*PST + tid] = sp[0] + sp[64] + sp[128] + sp[192];
            }
        }
    }

    // ================= last-block-per-batch combine ==========================
    __threadfence();
    __syncthreads();
    if (tid == 0) misc[0] = atomicAdd(&g_cnt[b], 1);
    __syncthreads();
    if (misc[0] != H_ - 1) return;

    __threadfence();   // acquire: all batch-b partials visible
    {
        float* fsh   = xs;          // [8][256]
        float* mred  = la;          // [128]
        float* tred  = la + 128;
        float* p0red = la + 256;
        float* p1red = la + 384;
        float* Mh    = la + 512;    // [8]
        float* Th    = la + 520;
        float* P0h   = la + 528;
        float* P1h   = la + 536;
        float* Ssh   = la + 1024;   // [8][64]
        int h = tid >> 4, seg = tid & 15;
        size_t bb = (size_t)b*H_*NH_;

        // pass 1: per-head global max
        float mx = -1e30f;
        #pragma unroll 4
        for (int r = seg*16; r < seg*16 + 16; r++)
            mx = fmaxf(mx, g_part[(bb + (size_t)r*NH_ + h)*PST + 64]);
        mred[h*16 + seg] = mx;
        __syncthreads();
        if (tid < 8) {
            float M = mred[tid*16];
            #pragma unroll
            for (int i = 1; i < 16; i++) M = fmaxf(M, mred[tid*16 + i]);
            Mh[tid] = M;
        }
        __syncthreads();

        // pass 2: f, T, P0, P1
        float M = Mh[h];
        float tacc = 0.f, p0acc = 0.f, p1acc = 0.f;
        #pragma unroll 4
        for (int r = seg*16; r < seg*16 + 16; r++) {
            const float* pbp = g_part + (bb + (size_t)r*NH_ + h)*PST;
            float f = __expf(pbp[64] - M);
            float Tf = pbp[65]*f;
            fsh[h*256 + r] = f;
            tacc += Tf;
            p0acc += Tf*(float)r;
            p1acc += pbp[66]*f;
        }
        tred[h*16+seg] = tacc; p0red[h*16+seg] = p0acc; p1red[h*16+seg] = p1acc;
        __syncthreads();
        if (tid < 8) {
            float T = 0.f, P0 = 0.f, P1 = 0.f;
            #pragma unroll
            for (int i = 0; i < 16; i++) {
                T += tred[tid*16+i]; P0 += p0red[tid*16+i]; P1 += p1red[tid*16+i];
            }
            Th[tid] = T; P0h[tid] = P0; P1h[tid] = P1;
        }
        __syncthreads();

        // S merge: thread = (c, 4 heads)
        {
            int c = tid & 63, hg = tid >> 6;
            #pragma unroll
            for (int j = 0; j < 4; j++) {
                int hh = hg*4 + j;
                float acc = 0.f;
                const float* sb = g_part + (bb + hh)*PST + c;
                const float* fb = fsh + hh*256;
                #pragma unroll 4
                for (int r = 0; r < 256; r++)
                    acc += sb[(size_t)r*NH_*PST] * fb[r];
                Ssh[hh*64 + c] = acc / Th[hh];
            }
        }
        __syncthreads();

        // values projection: thread = (h = tid>>4, 16 consecutive e)
        {
            int esub = tid & 15;
            const float4* ss = reinterpret_cast<const float4*>(Ssh + h*64);
            #pragma unroll
            for (int k = 0; k < 16; k++) {
                int e = esub*16 + k;
                float acc = bv[e];
                const float4* wv = reinterpret_cast<const float4*>(Wv + e*C_);
                #pragma unroll
                for (int c2 = 0; c2 < 16; c2++) {
                    float4 w = __ldg(wv + c2), sv = ss[c2];
                    acc += w.x*sv.x + w.y*sv.y + w.z*sv.z + w.w*sv.w;
                }
                out[(size_t)(b*NH_+h)*E_ + e] = acc;
            }
        }
        if (tid < 8) {
            float invT = 1.f/Th[tid];
            out[B_*NH_*E_ + (b*NH_+tid)*2]     = P0h[tid]*invT;
            out[B_*NH_*E_ + (b*NH_+tid)*2 + 1] = P1h[tid]*invT;
        }
        // reset for next launch/replay
        if (tid == 0) { g_cnt[b] = 0; g_flag[b] = 0; }
    }
}

extern "C" void kernel_launch(void* const* d_in, const int* in_sizes, int n_in,
                              void* d_out, int out_size)
{
    const float* x   = (const float*)d_in[0];
    const float* z   = (const float*)d_in[1];
    const float* pos = (const float*)d_in[2];
    const float* Wq  = (const float*)d_in[3];
    const float* bq  = (const float*)d_in[4];
    const float* Wk  = (const float*)d_in[5];
    const float* bk  = (const float*)d_in[6];
    const float* Wv  = (const float*)d_in[7];
    const float* bv  = (const float*)d_in[8];
    const float* Wp  = (const float*)d_in[9];
    const float* bp  = (const float*)d_in[10];
    float* out = (float*)d_out;

    cudaFuncSetAttribute(main_kernel, cudaFuncAttributeMaxDynamicSharedMemorySize,
                         SMEM_FLOATS * (int)sizeof(float));

    main_kernel<<<dim3(H_, B_), 128, SMEM_FLOATS * sizeof(float)>>>(
        x, z, pos, Wq, bq, Wk, bk, Wv, bv, Wp, bp, out);
}

// round 14
// speedup vs baseline: 2.0109x; 2.0109x over previous
#include <cuda_runtime.h>

#define B_ 8
#define C_ 64
#define H_ 256
#define W_ 256
#define E_ 256
#define NH_ 8
#define HD_ 32
#define NPIX (H_*W_)
#define PST 68

// smem floats: xs[256px*32c] | la[256*8] | w8[64*16] (aliased by red & Sp) | srow/sbv
#define XS_F   (256*32)
#define LA_F   (256*8)
#define W8_F   (64*16)
#define SMEM_FLOATS (XS_F + LA_F + W8_F + 16)

__device__ float g_wa[B_*NH_*C_];
__device__ float g_wb[B_*NH_*C_];
__device__ float g_wc[B_*NH_*C_];
__device__ float g_s [B_*NH_*3];
__device__ float g_part[(size_t)B_*H_*NH_*PST];

#define FMA2(a, x, w) asm("fma.rn.f32x2 %0, %1, %2, %0;" : "+l"(a) : "l"(x), "l"(w))

// ---------------------------------------------------------------------------
// Prep (r5 version)
// ---------------------------------------------------------------------------
__global__ void prep_kernel(const float* __restrict__ z,  const float* __restrict__ pos,
                            const float* __restrict__ Wq, const float* __restrict__ bq,
                            const float* __restrict__ Wk, const float* __restrict__ bk,
                            const float* __restrict__ Wp, const float* __restrict__ bp)
{
    int b = blockIdx.x >> 3, h = blockIdx.x & 7;
    __shared__ float tA[HD_], tB[HD_], tC[HD_];
    int tid = threadIdx.x;
    const float s = 0.1767766952966369f;  // 1/sqrt(32)

    int c2 = tid >> 2, sub = tid & 3;
    float wkr[8];
    #pragma unroll
    for (int d = 0; d < 8; d++)
        wkr[d] = __ldg(Wk + (h*HD_ + sub*8 + d)*C_ + c2);

    {
        int d = tid >> 3, q = tid & 7;
        int e = h*HD_ + d;
        const float4* zr = reinterpret_cast<const float4*>(z + b*C_);
        const float4* wq = reinterpret_cast<const float4*>(Wq + e*C_);
        float4 z0 = zr[q*2], z1 = zr[q*2+1];
        float4 w0 = __ldg(wq + q*2), w1 = __ldg(wq + q*2 + 1);
        float qv = z0.x*w0.x + z0.y*w0.y + z0.z*w0.z + z0.w*w0.w
                 + z1.x*w1.x + z1.y*w1.y + z1.z*w1.z + z1.w*w1.w;
        qv += __shfl_xor_sync(0xffffffffu, qv, 1);
        qv += __shfl_xor_sync(0xffffffffu, qv, 2);
        qv += __shfl_xor_sync(0xffffffffu, qv, 4);
        if (q == 0) {
            qv += bq[e];
            float wp0 = Wp[2*d], wp1 = Wp[2*d+1];
            float p0 = pos[(b*NH_+h)*2], p1 = pos[(b*NH_+h)*2+1];
            float cc = bp[d] - wp0*p0 - wp1*p1;
            tA[d] = qv*wp0*s; tB[d] = qv*wp1*s; tC[d] = qv*cc*s;
        }
    }
    __syncthreads();
    {
        float a = 0.f, bb = 0.f, cc = 0.f;
        #pragma unroll
        for (int d = 0; d < 8; d++) {
            int dd = sub*8 + d;
            float w = wkr[d];
            a += tA[dd]*w; bb += tB[dd]*w; cc += tC[dd]*w;
        }
        a  += __shfl_xor_sync(0xffffffffu, a, 1);
        bb += __shfl_xor_sync(0xffffffffu, bb, 1);
        cc += __shfl_xor_sync(0xffffffffu, cc, 1);
        a  += __shfl_xor_sync(0xffffffffu, a, 2);
        bb += __shfl_xor_sync(0xffffffffu, bb, 2);
        cc += __shfl_xor_sync(0xffffffffu, cc, 2);
        if (sub == 0) {
            int base = (b*NH_+h)*C_;
            g_wa[base+c2] = a; g_wb[base+c2] = bb; g_wc[base+c2] = cc;
        }
    }
    if (tid < 3) {
        const float* t = (tid==0) ? tA : ((tid==1) ? tB : tC);
        float sv = 0.f;
        #pragma unroll
        for (int d = 0; d < HD_; d++) sv += t[d]*bk[h*HD_ + d];
        g_s[(b*NH_+h)*3 + tid] = sv;
    }
}

// ---------------------------------------------------------------------------
// Staging: one 32-channel chunk into xs[256px][32c] swizzled
//   word(p,c) = p*32 + ((c + 8*(p&3) + (p>>2)) & 31)
// ---------------------------------------------------------------------------
__device__ __forceinline__ void stage_chunk(float* xs, const float* xg, int ch, int tid)
{
    #pragma unroll
    for (int r = 0; r < 2; r++) {
        float4 v[8];
        #pragma unroll
        for (int j = 0; j < 8; j++) {
            int idx = tid + (r*8 + j)*128;        // 0..2047
            int cl = idx >> 6, q = idx & 63;
            v[j] = __ldg(reinterpret_cast<const float4*>(xg + (size_t)(ch*32 + cl)*NPIX) + q);
        }
        #pragma unroll
        for (int j = 0; j < 8; j++) {
            int idx = tid + (r*8 + j)*128;
            int cl = idx >> 6, q = idx & 63;
            int base = q*128;                      // pixel 4q row
            xs[base      + ((cl + q     ) & 31)] = v[j].x;
            xs[base + 32 + ((cl + q +  8) & 31)] = v[j].y;
            xs[base + 64 + ((cl + q + 16) & 31)] = v[j].z;
            xs[base + 96 + ((cl + q + 24) & 31)] = v[j].w;
        }
    }
}

// ---------------------------------------------------------------------------
// Main: block = one row, 128 threads, occ 5 (20 warps/SM).
// Channel-chunked xs (32 KB); phase A accumulates across 2 chunk passes;
// phase B: chunk1 (resident) -> restage chunk0 -> chunk0.
// ---------------------------------------------------------------------------
__global__ void __launch_bounds__(128, 5) main_kernel(const float* __restrict__ x)
{
    extern __shared__ float sm[];
    float* xs   = sm;                      // [256*32]
    float* la   = sm + XS_F;               // [256][8]
    float* w8   = la + LA_F;               // [64][16]; aliased by red then Sp
    float* srow = w8 + W8_F;               // [8]
    float* sbv  = srow + 8;                // [8]
    float* red_m = w8, *red_t = w8 + 32, *red_pj = w8 + 64, *mfin = w8 + 96;

    int row = blockIdx.x, b = blockIdx.y;
    int tid = threadIdx.x;
    int warp = tid >> 5, lane = tid & 31;
    float rowf = (float)row;

    const float* xg = x + (size_t)b*C_*NPIX + (size_t)row*W_;

    // stage chunk 0
    stage_chunk(xs, xg, 0, tid);

    // per-row combined weights (once per block)
    if (tid < 64) {
        int c = tid;
        #pragma unroll
        for (int h = 0; h < 8; h++) {
            int gi = (b*NH_+h)*C_ + c;
            w8[c*16 + 2*h]     = g_wc[gi] + rowf*g_wa[gi];
            w8[c*16 + 2*h + 1] = g_wb[gi];
        }
    } else if (tid < 72) {
        int h = tid - 64;
        srow[h] = g_s[(b*NH_+h)*3+2] + rowf*g_s[(b*NH_+h)*3+0];
        sbv[h]  = g_s[(b*NH_+h)*3+1];
    }
    __syncthreads();

    // ---- Phase A over 2 chunk passes; 2 px/thread
    int p0 = tid, p1 = tid + 128;
    int G0 = ((p0 & 3) << 3) + (p0 >> 2);
    int G1 = ((p1 & 3) << 3) + (p1 >> 2);
    unsigned long long acc0[8], acc1[8];
    #pragma unroll
    for (int h = 0; h < 8; h++) { acc0[h] = 0ULL; acc1[h] = 0ULL; }

    #pragma unroll 1
    for (int ch = 0; ch < 2; ch++) {
        const float* xr0 = xs + p0*32;
        const float* xr1 = xs + p1*32;
        #pragma unroll 4
        for (int cl = 0; cl < 32; cl++) {
            float x0 = xr0[(cl + G0) & 31];
            float x1 = xr1[(cl + G1) & 31];
            unsigned long long xx0, xx1;
            asm("mov.b64 %0, {%1, %1};" : "=l"(xx0) : "f"(x0));
            asm("mov.b64 %0, {%1, %1};" : "=l"(xx1) : "f"(x1));
            const ulonglong2* wp = reinterpret_cast<const ulonglong2*>(w8 + (ch*32 + cl)*16);
            ulonglong2 wA = wp[0], wB = wp[1];
            FMA2(acc0[0], xx0, wA.x);  FMA2(acc1[0], xx1, wA.x);
            FMA2(acc0[1], xx0, wA.y);  FMA2(acc1[1], xx1, wA.y);
            FMA2(acc0[2], xx0, wB.x);  FMA2(acc1[2], xx1, wB.x);
            FMA2(acc0[3], xx0, wB.y);  FMA2(acc1[3], xx1, wB.y);
            ulonglong2 wC = wp[2], wD = wp[3];
            FMA2(acc0[4], xx0, wC.x);  FMA2(acc1[4], xx1, wC.x);
            FMA2(acc0[5], xx0, wC.y);  FMA2(acc1[5], xx1, wC.y);
            FMA2(acc0[6], xx0, wD.x);  FMA2(acc1[6], xx1, wD.x);
            FMA2(acc0[7], xx0, wD.y);  FMA2(acc1[7], xx1, wD.y);
        }
        __syncthreads();                 // xs reads of this chunk done
        if (ch == 0) {
            stage_chunk(xs, xg, 1, tid);
            __syncthreads();             // chunk1 ready
        }
    }

    float l0[8], l1[8];
    {
        float c0f = (float)p0, c1f = (float)p1;
        #pragma unroll
        for (int h = 0; h < 8; h++) {
            float r, bb;
            asm("mov.b64 {%0, %1}, %2;" : "=f"(r), "=f"(bb) : "l"(acc0[h]));
            l0[h] = (r + srow[h]) + c0f*(bb + sbv[h]);
            asm("mov.b64 {%0, %1}, %2;" : "=f"(r), "=f"(bb) : "l"(acc1[h]));
            l1[h] = (r + srow[h]) + c1f*(bb + sbv[h]);
        }
    }

    // ---- softmax over the row (red aliases w8; A-phase w8 reads are done)
    {
        float mh[8];
        #pragma unroll
        for (int h = 0; h < 8; h++) mh[h] = fmaxf(l0[h], l1[h]);
        #pragma unroll
        for (int o = 16; o; o >>= 1) {
            #pragma unroll
            for (int h = 0; h < 8; h++)
                mh[h] = fmaxf(mh[h], __shfl_xor_sync(0xffffffffu, mh[h], o));
        }
        if (lane == 0) {
            #pragma unroll
            for (int h = 0; h < 8; h++) red_m[warp*8 + h] = mh[h];
        }
        __syncthreads();
        if (tid < 8)
            mfin[tid] = fmaxf(fmaxf(red_m[tid], red_m[8+tid]),
                              fmaxf(red_m[16+tid], red_m[24+tid]));
        __syncthreads();

        float th[8], pjh[8], e0[8], e1[8];
        float c0f = (float)p0, c1f = (float)p1;
        #pragma unroll
        for (int h = 0; h < 8; h++) {
            float M = mfin[h];
            e0[h] = __expf(l0[h] - M);
            e1[h] = __expf(l1[h] - M);
            th[h]  = e0[h] + e1[h];
            pjh[h] = e0[h]*c0f + e1[h]*c1f;
        }
        *reinterpret_cast<float4*>(la + p0*8)     = make_float4(e0[0], e0[1], e0[2], e0[3]);
        *reinterpret_cast<float4*>(la + p0*8 + 4) = make_float4(e0[4], e0[5], e0[6], e0[7]);
        *reinterpret_cast<float4*>(la + p1*8)     = make_float4(e1[0], e1[1], e1[2], e1[3]);
        *reinterpret_cast<float4*>(la + p1*8 + 4) = make_float4(e1[4], e1[5], e1[6], e1[7]);

        #pragma unroll
        for (int o = 16; o; o >>= 1) {
            #pragma unroll
            for (int h = 0; h < 8; h++) {
                th[h]  += __shfl_xor_sync(0xffffffffu, th[h],  o);
                pjh[h] += __shfl_xor_sync(0xffffffffu, pjh[h], o);
            }
        }
        if (lane == 0) {
            #pragma unroll
            for (int h = 0; h < 8; h++) {
                red_t[warp*8 + h]  = th[h];
                red_pj[warp*8 + h] = pjh[h];
            }
        }
        __syncthreads();   // la + reductions ready
        if (tid < 8) {
            float T  = red_t[tid]  + red_t[8+tid]  + red_t[16+tid]  + red_t[24+tid];
            float PJ = red_pj[tid] + red_pj[8+tid] + red_pj[16+tid] + red_pj[24+tid];
            size_t pb = ((size_t)(b*H_ + row)*NH_ + tid)*PST;
            g_part[pb + 64] = mfin[tid];
            g_part[pb + 65] = T;
            g_part[pb + 66] = PJ;
        }
    }

    // ---- Phase B: chunk1 (resident) -> restage chunk0 -> chunk0
    size_t gb = (size_t)(b*H_ + row)*NH_;
    #pragma unroll 1
    for (int pass = 0; pass < 2; pass++) {
        int ch = 1 - pass;
        int cl = tid & 31, q4 = tid >> 5;
        unsigned long long acc[4];
        #pragma unroll
        for (int j = 0; j < 4; j++) acc[j] = 0ULL;
        int pbase = q4*64;
        #pragma unroll 4
        for (int i = 0; i < 64; i++) {
            int p = pbase + i;
            float xv = xs[p*32 + ((cl + ((p & 3) << 3) + (p >> 2)) & 31)];
            unsigned long long xx;
            asm("mov.b64 %0, {%1, %1};" : "=l"(xx) : "f"(xv));
            ulonglong2 eA = *reinterpret_cast<const ulonglong2*>(la + p*8);
            ulonglong2 eB = *reinterpret_cast<const ulonglong2*>(la + p*8 + 4);
            FMA2(acc[0], xx, eA.x);
            FMA2(acc[1], xx, eA.y);
            FMA2(acc[2], xx, eB.x);
            FMA2(acc[3], xx, eB.y);
        }
        __syncthreads();           // xs reads + any prior w8-region reads done
        float* Sp = w8;            // [8h][4q][32c] = 1024 floats
        #pragma unroll
        for (int j = 0; j < 4; j++) {
            float lo, hi;
            asm("mov.b64 {%0, %1}, %2;" : "=f"(lo), "=f"(hi) : "l"(acc[j]));
            Sp[(2*j  )*128 + q4*32 + cl] = lo;
            Sp[(2*j+1)*128 + q4*32 + cl] = hi;
        }
        __syncthreads();
        if (tid < 32) {
            #pragma unroll
            for (int h = 0; h < 8; h++) {
                const float* sp = Sp + h*128 + tid;
                g_part[(gb + h)*PST + ch*32 + tid] = sp[0] + sp[32] + sp[64] + sp[96];
            }
        }
        if (pass == 0) {
            __syncthreads();                  // Sp reads done before xs overwrite is irrelevant; xs reads done above
            stage_chunk(xs, xg, 0, tid);      // bring chunk0 back
            __syncthreads();
        }
    }
}

// ---------------------------------------------------------------------------
// Combine (r5 version)
// ---------------------------------------------------------------------------
__global__ void combine_kernel(const float* __restrict__ Wv, const float* __restrict__ bv,
                               float* __restrict__ out)
{
    int b = blockIdx.x >> 3, h = blockIdx.x & 7;
    __shared__ float fsh[256], Ssh[64], Sp[4][64];
    __shared__ float wred[8], wsum[8][3];
    __shared__ float Msh;
    int tid = threadIdx.x, warp = tid >> 5, lane = tid & 31;

    const float* pb = g_part + ((size_t)(b*H_+tid)*NH_ + h)*PST;
    float m = pb[64], T0 = pb[65], PJ0 = pb[66];

    float mm = m;
    #pragma unroll
    for (int o = 16; o; o >>= 1) mm = fmaxf(mm, __shfl_xor_sync(0xffffffffu, mm, o));
    if (lane == 0) wred[warp] = mm;
    __syncthreads();
    if (tid == 0) {
        float M = wred[0];
        #pragma unroll
        for (int i = 1; i < 8; i++) M = fmaxf(M, wred[i]);
        Msh = M;
    }
    __syncthreads();
    float M = Msh;
    float f = __expf(m - M);
    fsh[tid] = f;
    float Tl = T0*f, P0 = Tl*(float)tid, P1 = PJ0*f;
    #pragma unroll
    for (int o = 16; o; o >>= 1) {
        Tl += __shfl_xor_sync(0xffffffffu, Tl, o);
        P0 += __shfl_xor_sync(0xffffffffu, P0, o);
        P1 += __shfl_xor_sync(0xffffffffu, P1, o);
    }
    if (lane == 0) { wsum[warp][0] = Tl; wsum[warp][1] = P0; wsum[warp][2] = P1; }
    __syncthreads();
    float Tsh = 0.f, P0sh = 0.f, P1sh = 0.f;
    #pragma unroll
    for (int i = 0; i < 8; i++) { Tsh += wsum[i][0]; P0sh += wsum[i][1]; P1sh += wsum[i][2]; }

    int c = tid & 63, seg = tid >> 6;
    float sacc = 0.f;
    const float* pbase = g_part + ((size_t)(b*H_ + seg*64)*NH_ + h)*PST + c;
    #pragma unroll 4
    for (int i = 0; i < 64; i++)
        sacc += pbase[(size_t)i*NH_*PST] * fsh[seg*64 + i];
    Sp[seg][c] = sacc; __syncthreads();
    if (tid < 64) Ssh[tid] = (Sp[0][tid] + Sp[1][tid] + Sp[2][tid] + Sp[3][tid]) / Tsh;
    __syncthreads();

    int e = tid;
    float acc = bv[e];
    const float4* wv = reinterpret_cast<const float4*>(Wv + e*C_);
    const float4* ss = reinterpret_cast<const float4*>(Ssh);
    #pragma unroll
    for (int c2 = 0; c2 < 16; c2++) {
        float4 w = __ldg(wv + c2), sv = ss[c2];
        acc += w.x*sv.x + w.y*sv.y + w.z*sv.z + w.w*sv.w;
    }
    out[(size_t)(b*NH_+h)*E_ + e] = acc;

    if (tid == 0) {
        float invT = 1.f/Tsh;
        out[B_*NH_*E_ + (b*NH_+h)*2]     = P0sh*invT;
        out[B_*NH_*E_ + (b*NH_+h)*2 + 1] = P1sh*invT;
    }
}

extern "C" void kernel_launch(void* const* d_in, const int* in_sizes, int n_in,
                              void* d_out, int out_size)
{
    const float* x   = (const float*)d_in[0];
    const float* z   = (const float*)d_in[1];
    const float* pos = (const float*)d_in[2];
    const float* Wq  = (const float*)d_in[3];
    const float* bq  = (const float*)d_in[4];
    const float* Wk  = (const float*)d_in[5];
    const float* bk  = (const float*)d_in[6];
    const float* Wv  = (const float*)d_in[7];
    const float* bv  = (const float*)d_in[8];
    const float* Wp  = (const float*)d_in[9];
    const float* bp  = (const float*)d_in[10];
    float* out = (float*)d_out;

    cudaFuncSetAttribute(main_kernel, cudaFuncAttributeMaxDynamicSharedMemorySize,
                         SMEM_FLOATS * (int)sizeof(float));

    prep_kernel<<<B_*NH_, 256>>>(z, pos, Wq, bq, Wk, bk, Wp, bp);
    main_kernel<<<dim3(H_, B_), 128, SMEM_FLOATS * sizeof(float)>>>(x);
    combine_kernel<<<B_*NH_, 256>>>(Wv, bv, out);
}

// round 15
// speedup vs baseline: 2.0580x; 1.0234x over previous
#include <cuda_runtime.h>

#define B_ 8
#define C_ 64
#define H_ 256
#define W_ 256
#define E_ 256
#define NH_ 8
#define HD_ 32
#define NPIX (H_*W_)
#define PST 68

// smem floats: xs[16384] | la[2048] | w8[1024]  == 19456 floats = 77824 B -> occ 3
#define XS_F   (256*64)
#define LA_F   (256*8)
#define W8_F   (64*16)
#define SMEM_FLOATS (XS_F + LA_F + W8_F)

__device__ float g_wa[B_*NH_*C_];
__device__ float g_wb[B_*NH_*C_];
__device__ float g_wc[B_*NH_*C_];
__device__ float g_s [B_*NH_*3];
__device__ float g_part[(size_t)B_*H_*NH_*PST];

#define FMA2(a, x, w) asm("fma.rn.f32x2 %0, %1, %2, %0;" : "+l"(a) : "l"(x), "l"(w))

// ---------------------------------------------------------------------------
// Prep (r5 version, unchanged)
// ---------------------------------------------------------------------------
__global__ void prep_kernel(const float* __restrict__ z,  const float* __restrict__ pos,
                            const float* __restrict__ Wq, const float* __restrict__ bq,
                            const float* __restrict__ Wk, const float* __restrict__ bk,
                            const float* __restrict__ Wp, const float* __restrict__ bp)
{
    int b = blockIdx.x >> 3, h = blockIdx.x & 7;
    __shared__ float tA[HD_], tB[HD_], tC[HD_];
    int tid = threadIdx.x;
    const float s = 0.1767766952966369f;  // 1/sqrt(32)

    int c2 = tid >> 2, sub = tid & 3;
    float wkr[8];
    #pragma unroll
    for (int d = 0; d < 8; d++)
        wkr[d] = __ldg(Wk + (h*HD_ + sub*8 + d)*C_ + c2);

    {
        int d = tid >> 3, q = tid & 7;
        int e = h*HD_ + d;
        const float4* zr = reinterpret_cast<const float4*>(z + b*C_);
        const float4* wq = reinterpret_cast<const float4*>(Wq + e*C_);
        float4 z0 = zr[q*2], z1 = zr[q*2+1];
        float4 w0 = __ldg(wq + q*2), w1 = __ldg(wq + q*2 + 1);
        float qv = z0.x*w0.x + z0.y*w0.y + z0.z*w0.z + z0.w*w0.w
                 + z1.x*w1.x + z1.y*w1.y + z1.z*w1.z + z1.w*w1.w;
        qv += __shfl_xor_sync(0xffffffffu, qv, 1);
        qv += __shfl_xor_sync(0xffffffffu, qv, 2);
        qv += __shfl_xor_sync(0xffffffffu, qv, 4);
        if (q == 0) {
            qv += bq[e];
            float wp0 = Wp[2*d], wp1 = Wp[2*d+1];
            float p0 = pos[(b*NH_+h)*2], p1 = pos[(b*NH_+h)*2+1];
            float cc = bp[d] - wp0*p0 - wp1*p1;
            tA[d] = qv*wp0*s; tB[d] = qv*wp1*s; tC[d] = qv*cc*s;
        }
    }
    __syncthreads();
    {
        float a = 0.f, bb = 0.f, cc = 0.f;
        #pragma unroll
        for (int d = 0; d < 8; d++) {
            int dd = sub*8 + d;
            float w = wkr[d];
            a += tA[dd]*w; bb += tB[dd]*w; cc += tC[dd]*w;
        }
        a  += __shfl_xor_sync(0xffffffffu, a, 1);
        bb += __shfl_xor_sync(0xffffffffu, bb, 1);
        cc += __shfl_xor_sync(0xffffffffu, cc, 1);
        a  += __shfl_xor_sync(0xffffffffu, a, 2);
        bb += __shfl_xor_sync(0xffffffffu, bb, 2);
        cc += __shfl_xor_sync(0xffffffffu, cc, 2);
        if (sub == 0) {
            int base = (b*NH_+h)*C_;
            g_wa[base+c2] = a; g_wb[base+c2] = bb; g_wc[base+c2] = cc;
        }
    }
    if (tid < 3) {
        const float* t = (tid==0) ? tA : ((tid==1) ? tB : tC);
        float sv = 0.f;
        #pragma unroll
        for (int d = 0; d < HD_; d++) sv += t[d]*bk[h*HD_ + d];
        g_s[(b*NH_+h)*3 + tid] = sv;
    }
}

// ---------------------------------------------------------------------------
// Main: r5 instruction stream, smem packed to 76 KB -> occ 3 (12 warps/SM).
//   xs swizzle: word(p,c) = p*64 + ((c + 8*(p&3) + (p>>2)) & 63)
//   la stride 8; srow/sbv live in la[0..15] (dead before attn overwrites);
//   softmax red scratch + phase-B Sp alias w8 (dead after phase A).
// ---------------------------------------------------------------------------
__global__ void __launch_bounds__(128, 3) main_kernel(const float* __restrict__ x)
{
    extern __shared__ float sm[];
    float* xs   = sm;                      // [256*64] swizzled
    float* la   = sm + XS_F;               // [256][8] attn; [0..15] = srow/sbv early
    float* w8   = la + LA_F;               // [64][16]; aliased by red then Sp
    float* srow = la;                      // [8]  (dead before attn writes)
    float* sbv  = la + 8;                  // [8]
    float* red_m = w8, *red_t = w8 + 32, *red_pj = w8 + 64, *mfin = w8 + 96;

    int row = blockIdx.x, b = blockIdx.y;
    int tid = threadIdx.x;
    int warp = tid >> 5, lane = tid & 31;

    // stage x tile: 2 batches of 16 LDG.128 in flight, swizzled scatter
    {
        const float* xg = x + (size_t)b*C_*NPIX + (size_t)row*W_;
        #pragma unroll
        for (int half = 0; half < 2; half++) {
            float4 v[16];
            #pragma unroll
            for (int j = 0; j < 16; j++) {
                int idx = tid + (half*16 + j)*128;
                int c = idx >> 6, q = idx & 63;
                v[j] = __ldg(reinterpret_cast<const float4*>(xg + (size_t)c*NPIX) + q);
            }
            #pragma unroll
            for (int j = 0; j < 16; j++) {
                int idx = tid + (half*16 + j)*128;
                int c = idx >> 6, q = idx & 63;
                int base = q*4*64;
                xs[base       + ((c + q     ) & 63)] = v[j].x;
                xs[base + 64  + ((c + q +  8) & 63)] = v[j].y;
                xs[base + 128 + ((c + q + 16) & 63)] = v[j].z;
                xs[base + 192 + ((c + q + 24) & 63)] = v[j].w;
            }
        }
    }

    // per-row combined weights
    if (tid < 64) {
        int c = tid;
        float rf = (float)row;
        #pragma unroll
        for (int h = 0; h < 8; h++) {
            int gi = (b*NH_+h)*C_ + c;
            w8[c*16 + 2*h]     = g_wc[gi] + rf*g_wa[gi];
            w8[c*16 + 2*h + 1] = g_wb[gi];
        }
    } else if (tid < 72) {
        int h = tid - 64;
        srow[h] = g_s[(b*NH_+h)*3+2] + (float)row*g_s[(b*NH_+h)*3+0];
        sbv[h]  = g_s[(b*NH_+h)*3+1];
    }
    __syncthreads();

    // ---- Phase A: logits, 2 pixels per thread (cols tid, tid+128)
    int col0 = tid, col1 = tid + 128;
    float l0[8], l1[8];
    {
        unsigned long long acc0[8], acc1[8];
        #pragma unroll
        for (int h = 0; h < 8; h++) { acc0[h] = 0ULL; acc1[h] = 0ULL; }
        const float* xr0 = xs + col0*64;
        const float* xr1 = xs + col1*64;
        int G0 = ((col0 & 3) << 3) + (col0 >> 2);
        int G1 = ((col1 & 3) << 3) + (col1 >> 2);
        #pragma unroll 4
        for (int c = 0; c < 64; c++) {
            float x0 = xr0[(c + G0) & 63];
            float x1 = xr1[(c + G1) & 63];
            unsigned long long xx0, xx1;
            asm("mov.b64 %0, {%1, %1};" : "=l"(xx0) : "f"(x0));
            asm("mov.b64 %0, {%1, %1};" : "=l"(xx1) : "f"(x1));
            const ulonglong2* wp = reinterpret_cast<const ulonglong2*>(w8 + c*16);
            ulonglong2 wA = wp[0], wB = wp[1];
            FMA2(acc0[0], xx0, wA.x);  FMA2(acc1[0], xx1, wA.x);
            FMA2(acc0[1], xx0, wA.y);  FMA2(acc1[1], xx1, wA.y);
            FMA2(acc0[2], xx0, wB.x);  FMA2(acc1[2], xx1, wB.x);
            FMA2(acc0[3], xx0, wB.y);  FMA2(acc1[3], xx1, wB.y);
            ulonglong2 wC = wp[2], wD = wp[3];
            FMA2(acc0[4], xx0, wC.x);  FMA2(acc1[4], xx1, wC.x);
            FMA2(acc0[5], xx0, wC.y);  FMA2(acc1[5], xx1, wC.y);
            FMA2(acc0[6], xx0, wD.x);  FMA2(acc1[6], xx1, wD.x);
            FMA2(acc0[7], xx0, wD.y);  FMA2(acc1[7], xx1, wD.y);
        }
        float c0f = (float)col0, c1f = (float)col1;
        #pragma unroll
        for (int h = 0; h < 8; h++) {
            float r, bb;
            asm("mov.b64 {%0, %1}, %2;" : "=f"(r), "=f"(bb) : "l"(acc0[h]));
            l0[h] = (r + srow[h]) + c0f*(bb + sbv[h]);
            asm("mov.b64 {%0, %1}, %2;" : "=f"(r), "=f"(bb) : "l"(acc1[h]));
            l1[h] = (r + srow[h]) + c1f*(bb + sbv[h]);
        }
    }
    __syncthreads();   // all w8/srow reads done before red_* (aliases w8) is written

    // ---- softmax over the row (registers + shuffles)
    {
        float mh[8];
        #pragma unroll
        for (int h = 0; h < 8; h++) mh[h] = fmaxf(l0[h], l1[h]);
        #pragma unroll
        for (int o = 16; o; o >>= 1) {
            #pragma unroll
            for (int h = 0; h < 8; h++)
                mh[h] = fmaxf(mh[h], __shfl_xor_sync(0xffffffffu, mh[h], o));
        }
        if (lane == 0) {
            #pragma unroll
            for (int h = 0; h < 8; h++) red_m[warp*8 + h] = mh[h];
        }
        __syncthreads();
        if (tid < 8)
            mfin[tid] = fmaxf(fmaxf(red_m[tid], red_m[8+tid]),
                              fmaxf(red_m[16+tid], red_m[24+tid]));
        __syncthreads();

        float th[8], pjh[8], e0[8], e1[8];
        float c0f = (float)col0, c1f = (float)col1;
        #pragma unroll
        for (int h = 0; h < 8; h++) {
            float M = mfin[h];
            e0[h] = __expf(l0[h] - M);
            e1[h] = __expf(l1[h] - M);
            th[h]  = e0[h] + e1[h];
            pjh[h] = e0[h]*c0f + e1[h]*c1f;
        }
        *reinterpret_cast<float4*>(la + col0*8)     = make_float4(e0[0], e0[1], e0[2], e0[3]);
        *reinterpret_cast<float4*>(la + col0*8 + 4) = make_float4(e0[4], e0[5], e0[6], e0[7]);
        *reinterpret_cast<float4*>(la + col1*8)     = make_float4(e1[0], e1[1], e1[2], e1[3]);
        *reinterpret_cast<float4*>(la + col1*8 + 4) = make_float4(e1[4], e1[5], e1[6], e1[7]);

        #pragma unroll
        for (int o = 16; o; o >>= 1) {
            #pragma unroll
            for (int h = 0; h < 8; h++) {
                th[h]  += __shfl_xor_sync(0xffffffffu, th[h],  o);
                pjh[h] += __shfl_xor_sync(0xffffffffu, pjh[h], o);
            }
        }
        if (lane == 0) {
            #pragma unroll
            for (int h = 0; h < 8; h++) {
                red_t[warp*8 + h]  = th[h];
                red_pj[warp*8 + h] = pjh[h];
            }
        }
        __syncthreads();
        if (tid < 8) {
            float T  = red_t[tid]  + red_t[8+tid]  + red_t[16+tid]  + red_t[24+tid];
            float PJ = red_pj[tid] + red_pj[8+tid] + red_pj[16+tid] + red_pj[24+tid];
            size_t pb = ((size_t)(b*H_ + row)*NH_ + tid)*PST;
            g_part[pb + 64] = mfin[tid];
            g_part[pb + 65] = T;
            g_part[pb + 66] = PJ;
        }
    }

    // ---- Phase B: S[h][c] = sum_p e[p][h]*x[p][c], head-pairs via FMA2
    {
        int c = tid & 63, g = tid >> 6;
        unsigned long long acc[4];
        #pragma unroll
        for (int j = 0; j < 4; j++) acc[j] = 0ULL;
        int pbase = g*128;
        #pragma unroll 4
        for (int i = 0; i < 128; i++) {
            int p = pbase + i;
            int col = (c + ((p & 3) << 3) + (p >> 2)) & 63;
            float xv = xs[p*64 + col];
            unsigned long long xx;
            asm("mov.b64 %0, {%1, %1};" : "=l"(xx) : "f"(xv));
            ulonglong2 eA = *reinterpret_cast<const ulonglong2*>(la + p*8);
            ulonglong2 eB = *reinterpret_cast<const ulonglong2*>(la + p*8 + 4);
            FMA2(acc[0], xx, eA.x);
            FMA2(acc[1], xx, eA.y);
            FMA2(acc[2], xx, eB.x);
            FMA2(acc[3], xx, eB.y);
        }
        float* Sp = w8;  // reuse (red_t reads finished before this barrier)
        __syncthreads();
        *reinterpret_cast<ulonglong2*>(Sp + tid*8)     = make_ulonglong2(acc[0], acc[1]);
        *reinterpret_cast<ulonglong2*>(Sp + tid*8 + 4) = make_ulonglong2(acc[2], acc[3]);
        __syncthreads();
        if (tid < 64) {
            size_t chk = (size_t)(b*H_ + row)*NH_;
            #pragma unroll
            for (int h = 0; h < 8; h++)
                g_part[(chk + h)*PST + tid] = Sp[tid*8 + h] + Sp[(tid+64)*8 + h];
        }
    }
}

// ---------------------------------------------------------------------------
// Combine (r5 version)
// ---------------------------------------------------------------------------
__global__ void combine_kernel(const float* __restrict__ Wv, const float* __restrict__ bv,
                               float* __restrict__ out)
{
    int b = blockIdx.x >> 3, h = blockIdx.x & 7;
    __shared__ float fsh[256], Ssh[64], Sp[4][64];
    __shared__ float wred[8], wsum[8][3];
    __shared__ float Msh;
    int tid = threadIdx.x, warp = tid >> 5, lane = tid & 31;

    const float* pb = g_part + ((size_t)(b*H_+tid)*NH_ + h)*PST;
    float m = pb[64], T0 = pb[65], PJ0 = pb[66];

    float mm = m;
    #pragma unroll
    for (int o = 16; o; o >>= 1) mm = fmaxf(mm, __shfl_xor_sync(0xffffffffu, mm, o));
    if (lane == 0) wred[warp] = mm;
    __syncthreads();
    if (tid == 0) {
        float M = wred[0];
        #pragma unroll
        for (int i = 1; i < 8; i++) M = fmaxf(M, wred[i]);
        Msh = M;
    }
    __syncthreads();
    float M = Msh;
    float f = __expf(m - M);
    fsh[tid] = f;
    float Tl = T0*f, P0 = Tl*(float)tid, P1 = PJ0*f;
    #pragma unroll
    for (int o = 16; o; o >>= 1) {
        Tl += __shfl_xor_sync(0xffffffffu, Tl, o);
        P0 += __shfl_xor_sync(0xffffffffu, P0, o);
        P1 += __shfl_xor_sync(0xffffffffu, P1, o);
    }
    if (lane == 0) { wsum[warp][0] = Tl; wsum[warp][1] = P0; wsum[warp][2] = P1; }
    __syncthreads();
    float Tsh = 0.f, P0sh = 0.f, P1sh = 0.f;
    #pragma unroll
    for (int i = 0; i < 8; i++) { Tsh += wsum[i][0]; P0sh += wsum[i][1]; P1sh += wsum[i][2]; }

    int c = tid & 63, seg = tid >> 6;
    float sacc = 0.f;
    const float* pbase = g_part + ((size_t)(b*H_ + seg*64)*NH_ + h)*PST + c;
    #pragma unroll 4
    for (int i = 0; i < 64; i++)
        sacc += pbase[(size_t)i*NH_*PST] * fsh[seg*64 + i];
    Sp[seg][c] = sacc; __syncthreads();
    if (tid < 64) Ssh[tid] = (Sp[0][tid] + Sp[1][tid] + Sp[2][tid] + Sp[3][tid]) / Tsh;
    __syncthreads();

    int e = tid;
    float acc = bv[e];
    const float4* wv = reinterpret_cast<const float4*>(Wv + e*C_);
    const float4* ss = reinterpret_cast<const float4*>(Ssh);
    #pragma unroll
    for (int c2 = 0; c2 < 16; c2++) {
        float4 w = __ldg(wv + c2), sv = ss[c2];
        acc += w.x*sv.x + w.y*sv.y + w.z*sv.z + w.w*sv.w;
    }
    out[(size_t)(b*NH_+h)*E_ + e] = acc;

    if (tid == 0) {
        float invT = 1.f/Tsh;
        out[B_*NH_*E_ + (b*NH_+h)*2]     = P0sh*invT;
        out[B_*NH_*E_ + (b*NH_+h)*2 + 1] = P1sh*invT;
    }
}

extern "C" void kernel_launch(void* const* d_in, const int* in_sizes, int n_in,
                              void* d_out, int out_size)
{
    const float* x   = (const float*)d_in[0];
    const float* z   = (const float*)d_in[1];
    const float* pos = (const float*)d_in[2];
    const float* Wq  = (const float*)d_in[3];
    const float* bq  = (const float*)d_in[4];
    const float* Wk  = (const float*)d_in[5];
    const float* bk  = (const float*)d_in[6];
    const float* Wv  = (const float*)d_in[7];
    const float* bv  = (const float*)d_in[8];
    const float* Wp  = (const float*)d_in[9];
    const float* bp  = (const float*)d_in[10];
    float* out = (float*)d_out;

    cudaFuncSetAttribute(main_kernel, cudaFuncAttributeMaxDynamicSharedMemorySize,
                         SMEM_FLOATS * (int)sizeof(float));

    prep_kernel<<<B_*NH_, 256>>>(z, pos, Wq, bq, Wk, bk, Wp, bp);
    main_kernel<<<dim3(H_, B_), 128, SMEM_FLOATS * sizeof(float)>>>(x);
    combine_kernel<<<B_*NH_, 256>>>(Wv, bv, out);
}